// round 9
// baseline (speedup 1.0000x reference)
#include <cuda_runtime.h>
#include <cstdint>

// Problem constants
#define BATCH   8192
#define MSIZE   128
#define NBLK    32                 // ICOUNT = MCOUNT = OCOUNT
#define BN      (BATCH * MSIZE)    // 1048576 elems per c-slab

// Scratch: Y[c][b][n] (tf32-rounded), Z[c][b][m]  (128 MB each)
__device__ float g_Y[(size_t)NBLK * BN];
__device__ float g_Z[(size_t)NBLK * BN];

// ---------------- helpers ----------------
typedef unsigned long long ull;

__device__ __forceinline__ ull pk2(float lo, float hi) {
    ull r;
    asm("mov.b64 %0, {%1, %2};" : "=l"(r) : "f"(lo), "f"(hi));
    return r;
}
__device__ __forceinline__ void up2(ull v, float& lo, float& hi) {
    asm("mov.b64 {%0, %1}, %2;" : "=f"(lo), "=f"(hi) : "l"(v));
}
// packed fp32x2 FMA (Blackwell FFMA2): d = a*b + c componentwise
__device__ __forceinline__ ull ff2(ull a, ull b, ull c) {
    ull d;
    asm("fma.rn.f32x2 %0, %1, %2, %3;" : "=l"(d) : "l"(a), "l"(b), "l"(c));
    return d;
}
// round fp32 -> tf32 (fp32 bit pattern, low mantissa cleared)
__device__ __forceinline__ float tf32r(float v) {
    unsigned u;
    asm("cvt.rna.tf32.f32 %0, %1;" : "=r"(u) : "f"(v));
    return __uint_as_float(u);
}
__device__ __forceinline__ void mma_tf32(float& d0, float& d1, float& d2, float& d3,
                                         unsigned a0, unsigned a1, unsigned a2, unsigned a3,
                                         unsigned b0, unsigned b1) {
    asm volatile(
        "mma.sync.aligned.m16n8k8.row.col.f32.tf32.tf32.f32 "
        "{%0,%1,%2,%3}, {%4,%5,%6,%7}, {%8,%9}, {%0,%1,%2,%3};"
        : "+f"(d0), "+f"(d1), "+f"(d2), "+f"(d3)
        : "r"(a0), "r"(a1), "r"(a2), "r"(a3), "r"(b0), "r"(b1));
}

// ---------------- Stage 1 (unchanged — best measured) ----------------
// Y[c][b][n] = sum_i x[b, i*128+n] * W_in[c,i] + b_in[c]
__global__ void __launch_bounds__(128, 5) k_stage1(const float* __restrict__ x,
                                                   const float* __restrict__ Win,
                                                   const float* __restrict__ bin) {
    __shared__ ull wp[32][16];
    __shared__ ull bp[16];
    const int tid = threadIdx.x;
    for (int idx = tid; idx < 512; idx += 128) {
        const int cp = idx & 15, i = idx >> 4;
        wp[i][cp] = pk2(Win[(2 * cp) * 32 + i], Win[(2 * cp + 1) * 32 + i]);
    }
    if (tid < 16) bp[tid] = pk2(bin[2 * tid], bin[2 * tid + 1]);
    __syncthreads();

    const int n = tid;
    const size_t bA = (size_t)blockIdx.x * 2, bB = bA + 1;
    const float* xa = x + bA * 4096 + n;
    const float* xb = x + bB * 4096 + n;

#pragma unroll 1
    for (int h = 0; h < 2; h++) {
        const int cpb = h * 8;
        ull accA[8], accB[8];
#pragma unroll
        for (int j = 0; j < 8; j++) { accA[j] = bp[cpb + j]; accB[j] = bp[cpb + j]; }

#pragma unroll 8
        for (int i = 0; i < 32; i++) {
            const float va = xa[(size_t)i * 128];
            const float vb = xb[(size_t)i * 128];
            const ull ua = pk2(va, va);
            const ull ub = pk2(vb, vb);
#pragma unroll
            for (int jj = 0; jj < 4; jj++) {
                const ulonglong2 w2 = *(const ulonglong2*)&wp[i][cpb + 2 * jj];
                accA[2 * jj]     = ff2(ua, w2.x, accA[2 * jj]);
                accB[2 * jj]     = ff2(ub, w2.x, accB[2 * jj]);
                accA[2 * jj + 1] = ff2(ua, w2.y, accA[2 * jj + 1]);
                accB[2 * jj + 1] = ff2(ub, w2.y, accB[2 * jj + 1]);
            }
        }
#pragma unroll
        for (int j = 0; j < 8; j++) {
            const int cp = cpb + j;
            float l, hh;
            up2(accA[j], l, hh);
            g_Y[(size_t)(2 * cp) * BN + bA * 128 + n]     = tf32r(l);
            g_Y[(size_t)(2 * cp + 1) * BN + bA * 128 + n] = tf32r(hh);
            up2(accB[j], l, hh);
            g_Y[(size_t)(2 * cp) * BN + bB * 128 + n]     = tf32r(l);
            g_Y[(size_t)(2 * cp + 1) * BN + bB * 128 + n] = tf32r(hh);
        }
    }
}

// ---------------- Stage 2 (v2: 64-row tile, permuted-k smem, LDS.64 frags, 3 CTAs/SM) ----
// per c: Z[c][b][m] = sum_n Y[c][b][n] * W_mods[c][m][n] + b_mods[c][m]
// grid (128 b-tiles x 32 c), 256 threads (8 warps; warp = 32x32 subtile of 64x128).
// k-groups of 8 stored permuted [0,4,1,5,2,6,3,7] so frag pairs (tg,tg+4) are LDS.64.
// pos(k) = 2*(k&3) + ((k&7)>>2)
#define TILE_B 64
#define AS_LD 136   // = 8 mod 32 banks -> conflict-free LDS.64 phases
#define BS_LD 40
#define SMEM2_FLOATS (TILE_B * AS_LD + 128 * BS_LD + 128)

__global__ void __launch_bounds__(256, 3) k_stage2(const float* __restrict__ Wm,
                                                   const float* __restrict__ bmods) {
    extern __shared__ float sm[];
    float* As  = sm;                              // [64][AS_LD] permuted-k
    float* Bs  = sm + TILE_B * AS_LD;             // [128][BS_LD] permuted-k (one 32-k chunk)
    float* bmS = sm + TILE_B * AS_LD + 128 * BS_LD;

    const int tid = threadIdx.x;
    const int c   = blockIdx.y;
    const int bt  = blockIdx.x;

    const float* Wc = Wm + (size_t)c * 16384;

    // prefetch W chunk 0 into registers (4 float4 per thread)
    float4 pre[4];
#pragma unroll
    for (int j = 0; j < 4; j++) {
        const int i = tid + j * 256;               // 0..1023 over 128m x 8(float4 of k)
        const int mm = i >> 3, k0 = (i & 7) << 2;
        pre[j] = *(const float4*)(Wc + mm * 128 + k0);
    }

    // A tile: 64 rows x 128 k, contiguous 32KB of g_Y; scatter into permuted layout
    const float4* As4 = (const float4*)(g_Y + (size_t)c * BN + (size_t)bt * (TILE_B * 128));
#pragma unroll
    for (int i = tid; i < TILE_B * 32; i += 256) { // 2048 float4
        const int r = i >> 5, k0 = (i & 31) << 2;
        const float4 v = As4[i];
        float* dst = &As[r * AS_LD + (k0 & ~7) + ((k0 & 4) >> 2)];
        dst[0] = v.x; dst[2] = v.y; dst[4] = v.z; dst[6] = v.w;
    }
    if (tid < 128) bmS[tid] = bmods[c * 128 + tid];

    const int lane = tid & 31, warp = tid >> 5;
    const int g = lane >> 2, tg = lane & 3;
    const int wr = (warp & 1) * 32;        // row offset (2 warps over 64 rows)
    const int wc = (warp >> 1) * 32;       // col offset (4 warps over 128 cols)

    float acc[2][4][4];
#pragma unroll
    for (int rt = 0; rt < 2; rt++)
#pragma unroll
        for (int ct = 0; ct < 4; ct++)
#pragma unroll
            for (int j = 0; j < 4; j++) acc[rt][ct][j] = 0.0f;

#pragma unroll 1
    for (int kc = 0; kc < 4; kc++) {
        __syncthreads();  // As ready (kc=0) / Bs consumers done (kc>0)
        // commit prefetched W chunk to smem (tf32-rounded, permuted-k)
#pragma unroll
        for (int j = 0; j < 4; j++) {
            const int i = tid + j * 256;
            const int mm = i >> 3, k0 = (i & 7) << 2;
            const float4 v = pre[j];
            float* dst = &Bs[mm * BS_LD + (k0 & ~7) + ((k0 & 4) >> 2)];
            dst[0] = tf32r(v.x); dst[2] = tf32r(v.y); dst[4] = tf32r(v.z); dst[6] = tf32r(v.w);
        }
        __syncthreads();
        // prefetch next chunk (overlaps with MMA below)
        if (kc < 3) {
#pragma unroll
            for (int j = 0; j < 4; j++) {
                const int i = tid + j * 256;
                const int mm = i >> 3, k0 = (i & 7) << 2;
                pre[j] = *(const float4*)(Wc + mm * 128 + (kc + 1) * 32 + k0);
            }
        }

#pragma unroll
        for (int ks = 0; ks < 4; ks++) {
            const int gbA = (kc * 4 + ks) * 8 + 2 * tg;  // word offset within A row
            const int gbB = ks * 8 + 2 * tg;             // within B row (chunk-local)
            float2 aLo[2], aHi[2], bb[4];
#pragma unroll
            for (int rt = 0; rt < 2; rt++) {
                const int r0 = wr + rt * 16 + g;
                aLo[rt] = *(const float2*)&As[r0 * AS_LD + gbA];        // a0, a2
                aHi[rt] = *(const float2*)&As[(r0 + 8) * AS_LD + gbA];  // a1, a3
            }
#pragma unroll
            for (int ct = 0; ct < 4; ct++) {
                const int mcol = wc + ct * 8 + g;
                bb[ct] = *(const float2*)&Bs[mcol * BS_LD + gbB];       // b0, b1
            }
#pragma unroll
            for (int rt = 0; rt < 2; rt++)
#pragma unroll
                for (int ct = 0; ct < 4; ct++)
                    mma_tf32(acc[rt][ct][0], acc[rt][ct][1], acc[rt][ct][2], acc[rt][ct][3],
                             __float_as_uint(aLo[rt].x), __float_as_uint(aHi[rt].x),
                             __float_as_uint(aLo[rt].y), __float_as_uint(aHi[rt].y),
                             __float_as_uint(bb[ct].x),  __float_as_uint(bb[ct].y));
        }
    }

    // epilogue: add bias, write Z[c][b][m]
#pragma unroll
    for (int rt = 0; rt < 2; rt++) {
        const int r0 = wr + rt * 16 + g;
        const size_t gb0 = (size_t)c * BN + ((size_t)bt * TILE_B + r0) * 128;
#pragma unroll
        for (int ct = 0; ct < 4; ct++) {
            const int m0 = wc + ct * 8 + tg * 2;
            const float bv0 = bmS[m0], bv1 = bmS[m0 + 1];
            float2 v0 = make_float2(acc[rt][ct][0] + bv0, acc[rt][ct][1] + bv1);
            float2 v1 = make_float2(acc[rt][ct][2] + bv0, acc[rt][ct][3] + bv1);
            *(float2*)&g_Z[gb0 + m0]        = v0;   // row r0
            *(float2*)&g_Z[gb0 + 1024 + m0] = v1;   // row r0+8
        }
    }
}

// ---------------- Stage 3 (unchanged — best measured) ----------------
// out[b, m*32+o] = sum_c Z[c][b][m] * W_out[o,c] + b_out[o]
#define ST_LD 36
__global__ void __launch_bounds__(128, 5) k_stage3(const float* __restrict__ Wout,
                                                   const float* __restrict__ bout,
                                                   float* __restrict__ out) {
    __shared__ ull wp[32][16];
    __shared__ ull bp[16];
    __shared__ float sT[2][128 * ST_LD];
    const int tid = threadIdx.x;
    for (int idx = tid; idx < 512; idx += 128) {
        const int op = idx & 15, cc = idx >> 4;
        wp[cc][op] = pk2(Wout[(2 * op) * 32 + cc], Wout[(2 * op + 1) * 32 + cc]);
    }
    if (tid < 16) bp[tid] = pk2(bout[2 * tid], bout[2 * tid + 1]);
    __syncthreads();

    const int m = tid;
    const size_t bA = (size_t)blockIdx.x * 2, bB = bA + 1;
    const float* za0 = g_Z + bA * 128 + m;
    const float* zb0 = g_Z + bB * 128 + m;

#pragma unroll 1
    for (int h = 0; h < 2; h++) {
        const int opb = h * 8;
        ull accA[8], accB[8];
#pragma unroll
        for (int j = 0; j < 8; j++) { accA[j] = bp[opb + j]; accB[j] = bp[opb + j]; }

#pragma unroll 8
        for (int cc = 0; cc < 32; cc++) {
            const float za = za0[(size_t)cc * BN];
            const float zb = zb0[(size_t)cc * BN];
            const ull ua = pk2(za, za);
            const ull ub = pk2(zb, zb);
#pragma unroll
            for (int jj = 0; jj < 4; jj++) {
                const ulonglong2 w2 = *(const ulonglong2*)&wp[cc][opb + 2 * jj];
                accA[2 * jj]     = ff2(ua, w2.x, accA[2 * jj]);
                accB[2 * jj]     = ff2(ub, w2.x, accB[2 * jj]);
                accA[2 * jj + 1] = ff2(ua, w2.y, accA[2 * jj + 1]);
                accB[2 * jj + 1] = ff2(ub, w2.y, accB[2 * jj + 1]);
            }
        }
#pragma unroll
        for (int j = 0; j < 8; j++) {
            const int op = opb + j;
            float l, hh;
            up2(accA[j], l, hh);
            sT[0][m * ST_LD + 2 * op] = l; sT[0][m * ST_LD + 2 * op + 1] = hh;
            up2(accB[j], l, hh);
            sT[1][m * ST_LD + 2 * op] = l; sT[1][m * ST_LD + 2 * op + 1] = hh;
        }
    }
    __syncthreads();
#pragma unroll
    for (int k = 0; k < 8; k++) {
        const int j = (k * 128 + tid) * 4;
        const int mr = j >> 5, o = j & 31;
        *(float4*)&out[bA * 4096 + j] = *(const float4*)&sT[0][mr * ST_LD + o];
        *(float4*)&out[bB * 4096 + j] = *(const float4*)&sT[1][mr * ST_LD + o];
    }
}

// ---------------- launch ----------------
extern "C" void kernel_launch(void* const* d_in, const int* in_sizes, int n_in,
                              void* d_out, int out_size) {
    (void)in_sizes; (void)n_in; (void)out_size;
    const float* x      = (const float*)d_in[0];
    const float* W_in   = (const float*)d_in[1];
    const float* b_in   = (const float*)d_in[2];
    const float* W_mods = (const float*)d_in[3];
    const float* b_mods = (const float*)d_in[4];
    const float* W_out  = (const float*)d_in[5];
    const float* b_out  = (const float*)d_in[6];
    float* out = (float*)d_out;

    const int smem2 = SMEM2_FLOATS * (int)sizeof(float);  // 55808+512 bytes
    cudaFuncSetAttribute(k_stage2, cudaFuncAttributeMaxDynamicSharedMemorySize, smem2);

    k_stage1<<<BATCH / 2, 128>>>(x, W_in, b_in);
    k_stage2<<<dim3(BATCH / TILE_B, NBLK), 256, smem2>>>(W_mods, b_mods);
    k_stage3<<<BATCH / 2, 128>>>(W_out, b_out, out);
}

// round 10
// speedup vs baseline: 1.1322x; 1.1322x over previous
#include <cuda_runtime.h>
#include <cstdint>

// Problem constants
#define BATCH   8192
#define MSIZE   128
#define NBLK    32                 // ICOUNT = MCOUNT = OCOUNT
#define BN      (BATCH * MSIZE)    // 1048576 elems per c-slab

// Scratch: Y[c][b][n'] (tf32, k-permuted cols), Z[c][b][m] (128 MB each),
// Wp = k-permuted tf32 copy of W_mods (2 MB)
__device__ float g_Y[(size_t)NBLK * BN];
__device__ float g_Z[(size_t)NBLK * BN];
__device__ float g_Wp[(size_t)NBLK * 128 * 128];

// ---------------- helpers ----------------
typedef unsigned long long ull;

__device__ __forceinline__ ull pk2(float lo, float hi) {
    ull r;
    asm("mov.b64 %0, {%1, %2};" : "=l"(r) : "f"(lo), "f"(hi));
    return r;
}
__device__ __forceinline__ void up2(ull v, float& lo, float& hi) {
    asm("mov.b64 {%0, %1}, %2;" : "=f"(lo), "=f"(hi) : "l"(v));
}
__device__ __forceinline__ ull ff2(ull a, ull b, ull c) {
    ull d;
    asm("fma.rn.f32x2 %0, %1, %2, %3;" : "=l"(d) : "l"(a), "l"(b), "l"(c));
    return d;
}
__device__ __forceinline__ float tf32r(float v) {
    unsigned u;
    asm("cvt.rna.tf32.f32 %0, %1;" : "=r"(u) : "f"(v));
    return __uint_as_float(u);
}
__device__ __forceinline__ void mma_tf32(float& d0, float& d1, float& d2, float& d3,
                                         unsigned a0, unsigned a1, unsigned a2, unsigned a3,
                                         unsigned b0, unsigned b1) {
    asm volatile(
        "mma.sync.aligned.m16n8k8.row.col.f32.tf32.tf32.f32 "
        "{%0,%1,%2,%3}, {%4,%5,%6,%7}, {%8,%9}, {%0,%1,%2,%3};"
        : "+f"(d0), "+f"(d1), "+f"(d2), "+f"(d3)
        : "r"(a0), "r"(a1), "r"(a2), "r"(a3), "r"(b0), "r"(b1));
}
// k-permutation within 8-groups: perm(k) = (k&~7) + 2*(k&3) + ((k&7)>>2)
__device__ __forceinline__ int kperm(int k) {
    return (k & ~7) + ((k & 3) << 1) + ((k & 4) >> 2);
}

// ---------------- Prep: g_Wp = tf32(W_mods) with k-permuted last axis ----------------
// Output-contiguous float4; inverse perm within 8-group: half0 reads {0,4,1,5}, half1 {2,6,3,7}.
__global__ void __launch_bounds__(256) k_prep(const float* __restrict__ Wm) {
    const int idx  = blockIdx.x * 256 + threadIdx.x;   // 0..131071
    const int base = idx * 4;
    const int g8   = base & ~7;
    const int half = (base & 4) >> 2;
    float4 v;
    v.x = tf32r(Wm[g8 + (half ? 2 : 0)]);
    v.y = tf32r(Wm[g8 + (half ? 6 : 4)]);
    v.z = tf32r(Wm[g8 + (half ? 3 : 1)]);
    v.w = tf32r(Wm[g8 + (half ? 7 : 5)]);
    *(float4*)&g_Wp[base] = v;
}

// ---------------- Stage 1 ----------------
// Y[c][b][perm(n)] = tf32( sum_i x[b, i*128+n] * W_in[c,i] + b_in[c] )
__global__ void __launch_bounds__(128, 5) k_stage1(const float* __restrict__ x,
                                                   const float* __restrict__ Win,
                                                   const float* __restrict__ bin) {
    __shared__ ull wp[32][16];
    __shared__ ull bp[16];
    const int tid = threadIdx.x;
    for (int idx = tid; idx < 512; idx += 128) {
        const int cp = idx & 15, i = idx >> 4;
        wp[i][cp] = pk2(Win[(2 * cp) * 32 + i], Win[(2 * cp + 1) * 32 + i]);
    }
    if (tid < 16) bp[tid] = pk2(bin[2 * tid], bin[2 * tid + 1]);
    __syncthreads();

    const int n  = tid;
    const int pn = kperm(n);                 // permuted output column (free)
    const size_t bA = (size_t)blockIdx.x * 2, bB = bA + 1;
    const float* xa = x + bA * 4096 + n;
    const float* xb = x + bB * 4096 + n;

#pragma unroll 1
    for (int h = 0; h < 2; h++) {
        const int cpb = h * 8;
        ull accA[8], accB[8];
#pragma unroll
        for (int j = 0; j < 8; j++) { accA[j] = bp[cpb + j]; accB[j] = bp[cpb + j]; }

#pragma unroll 8
        for (int i = 0; i < 32; i++) {
            const float va = xa[(size_t)i * 128];
            const float vb = xb[(size_t)i * 128];
            const ull ua = pk2(va, va);
            const ull ub = pk2(vb, vb);
#pragma unroll
            for (int jj = 0; jj < 4; jj++) {
                const ulonglong2 w2 = *(const ulonglong2*)&wp[i][cpb + 2 * jj];
                accA[2 * jj]     = ff2(ua, w2.x, accA[2 * jj]);
                accB[2 * jj]     = ff2(ub, w2.x, accB[2 * jj]);
                accA[2 * jj + 1] = ff2(ua, w2.y, accA[2 * jj + 1]);
                accB[2 * jj + 1] = ff2(ub, w2.y, accB[2 * jj + 1]);
            }
        }
#pragma unroll
        for (int j = 0; j < 8; j++) {
            const int cp = cpb + j;
            float l, hh;
            up2(accA[j], l, hh);
            g_Y[(size_t)(2 * cp) * BN + bA * 128 + pn]     = tf32r(l);
            g_Y[(size_t)(2 * cp + 1) * BN + bA * 128 + pn] = tf32r(hh);
            up2(accB[j], l, hh);
            g_Y[(size_t)(2 * cp) * BN + bB * 128 + pn]     = tf32r(l);
            g_Y[(size_t)(2 * cp + 1) * BN + bB * 128 + pn] = tf32r(hh);
        }
    }
}

// ---------------- Stage 2 (R5 config + LDS.64 fragments via pre-permuted data) ----------
// per c: Z[c][b][m] = sum_n Y[c][b][n] * W_mods[c][m][n] + b_mods[c][m]
// grid (64 b-tiles x 32 c), 256 threads (8 warps; warp = 64x32 subtile of 128x128).
// Both g_Y and g_Wp are k-permuted -> verbatim float4 copies into smem, LDS.64 frags.
#define AS_LD 136   // ≡8 mod 32 banks: conflict-free LDS.64 phases
#define BS_LD 40
#define SMEM2_FLOATS (128 * AS_LD + 128 * BS_LD + 128)

__global__ void __launch_bounds__(256, 2) k_stage2(const float* __restrict__ bmods) {
    extern __shared__ float sm[];
    float* As  = sm;                             // [128][AS_LD] (k-permuted)
    float* Bs  = sm + 128 * AS_LD;               // [128][BS_LD] (k-permuted, 32-k chunk)
    float* bmS = sm + 128 * AS_LD + 128 * BS_LD; // [128]

    const int tid = threadIdx.x;
    const int c   = blockIdx.y;
    const int bt  = blockIdx.x;

    const float* Wc = g_Wp + (size_t)c * 16384;  // pre-rounded, pre-permuted

    // prefetch W chunk 0 into registers (4 float4 per thread)
    float4 pre[4];
#pragma unroll
    for (int j = 0; j < 4; j++) {
        const int i = tid + j * 256;               // 0..1023 over 128m x 8 quad-k
        const int mm = i >> 3, k0 = (i & 7) << 2;
        pre[j] = *(const float4*)(Wc + mm * 128 + k0);
    }

    // A tile: contiguous 64KB of g_Y (tf32 + permuted already)
    const float4* As4 = (const float4*)(g_Y + (size_t)c * BN + (size_t)bt * 16384);
#pragma unroll
    for (int i = tid; i < 4096; i += 256) {
        const int r = i >> 5, cc = (i & 31) << 2;
        *(float4*)&As[r * AS_LD + cc] = As4[i];
    }
    if (tid < 128) bmS[tid] = bmods[c * 128 + tid];

    const int lane = tid & 31, warp = tid >> 5;
    const int g = lane >> 2, tg = lane & 3;
    const int wr = (warp & 1) * 64;        // row offset (2 warps over 128 rows)
    const int wc = (warp >> 1) * 32;       // col offset (4 warps over 128 cols)

    float acc[4][4][4];
#pragma unroll
    for (int rt = 0; rt < 4; rt++)
#pragma unroll
        for (int ct = 0; ct < 4; ct++)
#pragma unroll
            for (int j = 0; j < 4; j++) acc[rt][ct][j] = 0.0f;

#pragma unroll 1
    for (int kc = 0; kc < 4; kc++) {
        __syncthreads();  // As ready (kc=0) / Bs consumers done (kc>0)
        // commit prefetched W chunk to smem (verbatim STS.128)
#pragma unroll
        for (int j = 0; j < 4; j++) {
            const int i = tid + j * 256;
            const int mm = i >> 3, k0 = (i & 7) << 2;
            *(float4*)&Bs[mm * BS_LD + k0] = pre[j];
        }
        __syncthreads();
        // prefetch next chunk (overlaps with MMA below)
        if (kc < 3) {
#pragma unroll
            for (int j = 0; j < 4; j++) {
                const int i = tid + j * 256;
                const int mm = i >> 3, k0 = (i & 7) << 2;
                pre[j] = *(const float4*)(Wc + mm * 128 + (kc + 1) * 32 + k0);
            }
        }

#pragma unroll
        for (int ks = 0; ks < 4; ks++) {
            const int gbA = (kc * 4 + ks) * 8 + 2 * tg;  // permuted word offset in A row
            const int gbB = ks * 8 + 2 * tg;             // within B chunk row
            float2 aLo[4], aHi[4], bb[4];
#pragma unroll
            for (int rt = 0; rt < 4; rt++) {
                const int r0 = wr + rt * 16 + g;
                aLo[rt] = *(const float2*)&As[r0 * AS_LD + gbA];        // (a0, a2)
                aHi[rt] = *(const float2*)&As[(r0 + 8) * AS_LD + gbA];  // (a1, a3)
            }
#pragma unroll
            for (int ct = 0; ct < 4; ct++) {
                const int mcol = wc + ct * 8 + g;
                bb[ct] = *(const float2*)&Bs[mcol * BS_LD + gbB];       // (b0, b1)
            }
#pragma unroll
            for (int rt = 0; rt < 4; rt++)
#pragma unroll
                for (int ct = 0; ct < 4; ct++)
                    mma_tf32(acc[rt][ct][0], acc[rt][ct][1], acc[rt][ct][2], acc[rt][ct][3],
                             __float_as_uint(aLo[rt].x), __float_as_uint(aHi[rt].x),
                             __float_as_uint(aLo[rt].y), __float_as_uint(aHi[rt].y),
                             __float_as_uint(bb[ct].x),  __float_as_uint(bb[ct].y));
        }
    }

    // epilogue: add bias, write Z[c][b][m]
#pragma unroll
    for (int rt = 0; rt < 4; rt++) {
        const int r0 = wr + rt * 16 + g;
        const size_t gb0 = (size_t)c * BN + ((size_t)bt * 128 + r0) * 128;
#pragma unroll
        for (int ct = 0; ct < 4; ct++) {
            const int m0 = wc + ct * 8 + tg * 2;
            const float bv0 = bmS[m0], bv1 = bmS[m0 + 1];
            float2 v0 = make_float2(acc[rt][ct][0] + bv0, acc[rt][ct][1] + bv1);
            float2 v1 = make_float2(acc[rt][ct][2] + bv0, acc[rt][ct][3] + bv1);
            *(float2*)&g_Z[gb0 + m0]        = v0;   // row r0
            *(float2*)&g_Z[gb0 + 1024 + m0] = v1;   // row r0+8
        }
    }
}

// ---------------- Stage 3 (unchanged — best measured) ----------------
// out[b, m*32+o] = sum_c Z[c][b][m] * W_out[o,c] + b_out[o]
#define ST_LD 36
__global__ void __launch_bounds__(128, 5) k_stage3(const float* __restrict__ Wout,
                                                   const float* __restrict__ bout,
                                                   float* __restrict__ out) {
    __shared__ ull wp[32][16];
    __shared__ ull bp[16];
    __shared__ float sT[2][128 * ST_LD];
    const int tid = threadIdx.x;
    for (int idx = tid; idx < 512; idx += 128) {
        const int op = idx & 15, cc = idx >> 4;
        wp[cc][op] = pk2(Wout[(2 * op) * 32 + cc], Wout[(2 * op + 1) * 32 + cc]);
    }
    if (tid < 16) bp[tid] = pk2(bout[2 * tid], bout[2 * tid + 1]);
    __syncthreads();

    const int m = tid;
    const size_t bA = (size_t)blockIdx.x * 2, bB = bA + 1;
    const float* za0 = g_Z + bA * 128 + m;
    const float* zb0 = g_Z + bB * 128 + m;

#pragma unroll 1
    for (int h = 0; h < 2; h++) {
        const int opb = h * 8;
        ull accA[8], accB[8];
#pragma unroll
        for (int j = 0; j < 8; j++) { accA[j] = bp[opb + j]; accB[j] = bp[opb + j]; }

#pragma unroll 8
        for (int cc = 0; cc < 32; cc++) {
            const float za = za0[(size_t)cc * BN];
            const float zb = zb0[(size_t)cc * BN];
            const ull ua = pk2(za, za);
            const ull ub = pk2(zb, zb);
#pragma unroll
            for (int jj = 0; jj < 4; jj++) {
                const ulonglong2 w2 = *(const ulonglong2*)&wp[cc][opb + 2 * jj];
                accA[2 * jj]     = ff2(ua, w2.x, accA[2 * jj]);
                accB[2 * jj]     = ff2(ub, w2.x, accB[2 * jj]);
                accA[2 * jj + 1] = ff2(ua, w2.y, accA[2 * jj + 1]);
                accB[2 * jj + 1] = ff2(ub, w2.y, accB[2 * jj + 1]);
            }
        }
#pragma unroll
        for (int j = 0; j < 8; j++) {
            const int op = opb + j;
            float l, hh;
            up2(accA[j], l, hh);
            sT[0][m * ST_LD + 2 * op] = l; sT[0][m * ST_LD + 2 * op + 1] = hh;
            up2(accB[j], l, hh);
            sT[1][m * ST_LD + 2 * op] = l; sT[1][m * ST_LD + 2 * op + 1] = hh;
        }
    }
    __syncthreads();
#pragma unroll
    for (int k = 0; k < 8; k++) {
        const int j = (k * 128 + tid) * 4;
        const int mr = j >> 5, o = j & 31;
        *(float4*)&out[bA * 4096 + j] = *(const float4*)&sT[0][mr * ST_LD + o];
        *(float4*)&out[bB * 4096 + j] = *(const float4*)&sT[1][mr * ST_LD + o];
    }
}

// ---------------- launch ----------------
extern "C" void kernel_launch(void* const* d_in, const int* in_sizes, int n_in,
                              void* d_out, int out_size) {
    (void)in_sizes; (void)n_in; (void)out_size;
    const float* x      = (const float*)d_in[0];
    const float* W_in   = (const float*)d_in[1];
    const float* b_in   = (const float*)d_in[2];
    const float* W_mods = (const float*)d_in[3];
    const float* b_mods = (const float*)d_in[4];
    const float* W_out  = (const float*)d_in[5];
    const float* b_out  = (const float*)d_in[6];
    float* out = (float*)d_out;

    const int smem2 = SMEM2_FLOATS * (int)sizeof(float);  // 90624 bytes
    cudaFuncSetAttribute(k_stage2, cudaFuncAttributeMaxDynamicSharedMemorySize, smem2);

    k_prep  <<<512, 256>>>(W_mods);
    k_stage1<<<BATCH / 2, 128>>>(x, W_in, b_in);
    k_stage2<<<dim3(BATCH / 128, NBLK), 256, smem2>>>(b_mods);
    k_stage3<<<BATCH / 2, 128>>>(W_out, b_out, out);
}

// round 13
// speedup vs baseline: 1.1426x; 1.0092x over previous
#include <cuda_runtime.h>
#include <cstdint>

// Problem constants
#define BATCH   8192
#define MSIZE   128
#define NBLK    32                 // ICOUNT = MCOUNT = OCOUNT
#define BN      (BATCH * MSIZE)    // 1048576 elems per c-slab

// Scratch: Y[c][b][n] (tf32-rounded), Z[c][b][m]  (128 MB each)
__device__ float g_Y[(size_t)NBLK * BN];
__device__ float g_Z[(size_t)NBLK * BN];

// ---------------- helpers ----------------
typedef unsigned long long ull;

__device__ __forceinline__ ull pk2(float lo, float hi) {
    ull r;
    asm("mov.b64 %0, {%1, %2};" : "=l"(r) : "f"(lo), "f"(hi));
    return r;
}
__device__ __forceinline__ void up2(ull v, float& lo, float& hi) {
    asm("mov.b64 {%0, %1}, %2;" : "=f"(lo), "=f"(hi) : "l"(v));
}
// packed fp32x2 FMA (Blackwell FFMA2): d = a*b + c componentwise
__device__ __forceinline__ ull ff2(ull a, ull b, ull c) {
    ull d;
    asm("fma.rn.f32x2 %0, %1, %2, %3;" : "=l"(d) : "l"(a), "l"(b), "l"(c));
    return d;
}
// round fp32 -> tf32 (fp32 bit pattern, low mantissa cleared)
__device__ __forceinline__ float tf32r(float v) {
    unsigned u;
    asm("cvt.rna.tf32.f32 %0, %1;" : "=r"(u) : "f"(v));
    return __uint_as_float(u);
}
__device__ __forceinline__ void mma_tf32(float& d0, float& d1, float& d2, float& d3,
                                         unsigned a0, unsigned a1, unsigned a2, unsigned a3,
                                         unsigned b0, unsigned b1) {
    asm volatile(
        "mma.sync.aligned.m16n8k8.row.col.f32.tf32.tf32.f32 "
        "{%0,%1,%2,%3}, {%4,%5,%6,%7}, {%8,%9}, {%0,%1,%2,%3};"
        : "+f"(d0), "+f"(d1), "+f"(d2), "+f"(d3)
        : "r"(a0), "r"(a1), "r"(a2), "r"(a3), "r"(b0), "r"(b1));
}

// ---------------- Stage 1 (wide-load version) ----------------
// Y[c][b][n] = sum_i x[b, i*128+n] * W_in[c,i] + b_in[c]
// 128 threads: row = tid>>6 (2 rows/CTA), n-pair p = tid&63 (n0 = 2p).
// Per i: ONE LDG.64; stores are STG.64. Two half-passes over c for low reg state.
__global__ void __launch_bounds__(128, 5) k_stage1(const float* __restrict__ x,
                                                   const float* __restrict__ Win,
                                                   const float* __restrict__ bin) {
    __shared__ ull wp[32][16];  // [i][cp] = (W_in[2cp][i], W_in[2cp+1][i])
    __shared__ ull bp[16];
    const int tid = threadIdx.x;
    for (int idx = tid; idx < 512; idx += 128) {
        const int cp = idx & 15, i = idx >> 4;
        wp[i][cp] = pk2(Win[(2 * cp) * 32 + i], Win[(2 * cp + 1) * 32 + i]);
    }
    if (tid < 16) bp[tid] = pk2(bin[2 * tid], bin[2 * tid + 1]);
    __syncthreads();

    const int row = tid >> 6;
    const int n0  = (tid & 63) * 2;
    const size_t b = (size_t)blockIdx.x * 2 + row;
    const float* xr = x + b * 4096 + n0;

#pragma unroll 1
    for (int h = 0; h < 2; h++) {
        const int cpb = h * 8;
        ull acc0[8], acc1[8];   // acc0: n0, acc1: n0+1 (each packed over c-pair)
#pragma unroll
        for (int j = 0; j < 8; j++) { acc0[j] = bp[cpb + j]; acc1[j] = bp[cpb + j]; }

#pragma unroll 8
        for (int i = 0; i < 32; i++) {
            const float2 xv = *(const float2*)&xr[(size_t)i * 128];
            const ull u0 = pk2(xv.x, xv.x);
            const ull u1 = pk2(xv.y, xv.y);
#pragma unroll
            for (int jj = 0; jj < 4; jj++) {
                const ulonglong2 w2 = *(const ulonglong2*)&wp[i][cpb + 2 * jj];
                acc0[2 * jj]     = ff2(u0, w2.x, acc0[2 * jj]);
                acc1[2 * jj]     = ff2(u1, w2.x, acc1[2 * jj]);
                acc0[2 * jj + 1] = ff2(u0, w2.y, acc0[2 * jj + 1]);
                acc1[2 * jj + 1] = ff2(u1, w2.y, acc1[2 * jj + 1]);
            }
        }
#pragma unroll
        for (int j = 0; j < 8; j++) {
            const int cp = cpb + j;
            float l0, h0, l1, h1;
            up2(acc0[j], l0, h0);
            up2(acc1[j], l1, h1);
            *(float2*)&g_Y[(size_t)(2 * cp) * BN + b * 128 + n0]     = make_float2(tf32r(l0), tf32r(l1));
            *(float2*)&g_Y[(size_t)(2 * cp + 1) * BN + b * 128 + n0] = make_float2(tf32r(h0), tf32r(h1));
        }
    }
}

// ---------------- Stage 2 (exact R7 config — best measured) ----------------
// per c: Z[c][b][m] = sum_n Y[c][b][n] * W_mods[c][m][n] + b_mods[c][m]
// grid (64 batch tiles, 32 c), 256 threads (8 warps; warp = 64x32 subtile of 128x128).
#define AS_LD 132
#define BS_LD 36
#define SMEM2_FLOATS (128 * AS_LD + 128 * BS_LD + 128)

__global__ void __launch_bounds__(256, 2) k_stage2(const float* __restrict__ Wm,
                                                   const float* __restrict__ bmods) {
    extern __shared__ float sm[];
    float* As  = sm;                             // [128][AS_LD]
    float* Bs  = sm + 128 * AS_LD;               // [128][BS_LD]  (m-major, k minor)
    float* bmS = sm + 128 * AS_LD + 128 * BS_LD; // [128]

    const int tid = threadIdx.x;
    const int c   = blockIdx.y;
    const int bt  = blockIdx.x;

    const float* Wc = Wm + (size_t)c * 16384;

    // prefetch W chunk 0 into registers (4 float4 per thread)
    float4 pre[4];
#pragma unroll
    for (int j = 0; j < 4; j++) {
        const int i = tid + j * 256;               // 0..1023
        const int mm = i >> 3, cc = (i & 7) << 2;
        pre[j] = *(const float4*)(Wc + mm * 128 + cc);
    }

    // A tile: contiguous 64KB of g_Y (already tf32-rounded)
    const float4* As4 = (const float4*)(g_Y + (size_t)c * BN + (size_t)bt * 16384);
#pragma unroll
    for (int i = tid; i < 4096; i += 256) {
        const int r = i >> 5, cc = (i & 31) << 2;
        *(float4*)&As[r * AS_LD + cc] = As4[i];
    }
    if (tid < 128) bmS[tid] = bmods[c * 128 + tid];

    const int lane = tid & 31, warp = tid >> 5;
    const int g = lane >> 2, tg = lane & 3;
    const int wr = (warp & 1) * 64;        // row offset (2 warps over 128 rows)
    const int wc = (warp >> 1) * 32;       // col offset (4 warps over 128 cols)

    float acc[4][4][4];
#pragma unroll
    for (int rt = 0; rt < 4; rt++)
#pragma unroll
        for (int ct = 0; ct < 4; ct++)
#pragma unroll
            for (int j = 0; j < 4; j++) acc[rt][ct][j] = 0.0f;

#pragma unroll 1
    for (int kc = 0; kc < 4; kc++) {
        __syncthreads();  // A ready (kc=0) / Bs consumers done (kc>0)
        // commit prefetched W chunk to smem (tf32-rounded)
#pragma unroll
        for (int j = 0; j < 4; j++) {
            const int i = tid + j * 256;
            const int mm = i >> 3, cc = (i & 7) << 2;
            float4 v = pre[j];
            v.x = tf32r(v.x); v.y = tf32r(v.y); v.z = tf32r(v.z); v.w = tf32r(v.w);
            *(float4*)&Bs[mm * BS_LD + cc] = v;
        }
        __syncthreads();
        // prefetch next chunk (overlaps with MMA below)
        if (kc < 3) {
#pragma unroll
            for (int j = 0; j < 4; j++) {
                const int i = tid + j * 256;
                const int mm = i >> 3, cc = (i & 7) << 2;
                pre[j] = *(const float4*)(Wc + mm * 128 + (kc + 1) * 32 + cc);
            }
        }

#pragma unroll
        for (int ks = 0; ks < 4; ks++) {
            const int kA = kc * 32 + ks * 8;
            const int kB = ks * 8;
            unsigned a0[4], a1[4], a2[4], a3[4], b0[4], b1[4];
#pragma unroll
            for (int rt = 0; rt < 4; rt++) {
                const int r0 = wr + rt * 16 + g;
                a0[rt] = __float_as_uint(As[r0 * AS_LD + kA + tg]);
                a1[rt] = __float_as_uint(As[(r0 + 8) * AS_LD + kA + tg]);
                a2[rt] = __float_as_uint(As[r0 * AS_LD + kA + tg + 4]);
                a3[rt] = __float_as_uint(As[(r0 + 8) * AS_LD + kA + tg + 4]);
            }
#pragma unroll
            for (int ct = 0; ct < 4; ct++) {
                const int mcol = wc + ct * 8 + g;
                b0[ct] = __float_as_uint(Bs[mcol * BS_LD + kB + tg]);
                b1[ct] = __float_as_uint(Bs[mcol * BS_LD + kB + tg + 4]);
            }
#pragma unroll
            for (int rt = 0; rt < 4; rt++)
#pragma unroll
                for (int ct = 0; ct < 4; ct++)
                    mma_tf32(acc[rt][ct][0], acc[rt][ct][1], acc[rt][ct][2], acc[rt][ct][3],
                             a0[rt], a1[rt], a2[rt], a3[rt], b0[ct], b1[ct]);
        }
    }

    // epilogue: add bias, write Z[c][b][m]
#pragma unroll
    for (int rt = 0; rt < 4; rt++) {
        const int r0 = wr + rt * 16 + g;
        const size_t gb0 = (size_t)c * BN + ((size_t)bt * 128 + r0) * 128;
#pragma unroll
        for (int ct = 0; ct < 4; ct++) {
            const int m0 = wc + ct * 8 + tg * 2;
            const float bv0 = bmS[m0], bv1 = bmS[m0 + 1];
            float2 v0 = make_float2(acc[rt][ct][0] + bv0, acc[rt][ct][1] + bv1);
            float2 v1 = make_float2(acc[rt][ct][2] + bv0, acc[rt][ct][3] + bv1);
            *(float2*)&g_Z[gb0 + m0]        = v0;   // row r0
            *(float2*)&g_Z[gb0 + 1024 + m0] = v1;   // row r0+8
        }
    }
}

// ---------------- Stage 3 (wide-load version) ----------------
// out[b, m*32+o] = sum_c Z[c][b][m] * W_out[o,c] + b_out[o]
// 128 threads: row = tid>>6, m-pair p = tid&63 (m0 = 2p). Per c: ONE LDG.64.
#define ST_LD 36
__global__ void __launch_bounds__(128, 5) k_stage3(const float* __restrict__ Wout,
                                                   const float* __restrict__ bout,
                                                   float* __restrict__ out) {
    __shared__ ull wp[32][16];  // [c][op] = (W_out[2op][c], W_out[2op+1][c])
    __shared__ ull bp[16];
    __shared__ float sT[2][128 * ST_LD];
    const int tid = threadIdx.x;
    for (int idx = tid; idx < 512; idx += 128) {
        const int op = idx & 15, cc = idx >> 4;
        wp[cc][op] = pk2(Wout[(2 * op) * 32 + cc], Wout[(2 * op + 1) * 32 + cc]);
    }
    if (tid < 16) bp[tid] = pk2(bout[2 * tid], bout[2 * tid + 1]);
    __syncthreads();

    const int row = tid >> 6;
    const int m0  = (tid & 63) * 2;
    const size_t bA = (size_t)blockIdx.x * 2;
    const size_t b  = bA + row;
    const float* zr = g_Z + b * 128 + m0;

#pragma unroll 1
    for (int h = 0; h < 2; h++) {
        const int opb = h * 8;
        ull acc0[8], acc1[8];   // acc0: m0, acc1: m0+1 (each packed over o-pair)
#pragma unroll
        for (int j = 0; j < 8; j++) { acc0[j] = bp[opb + j]; acc1[j] = bp[opb + j]; }

#pragma unroll 8
        for (int cc = 0; cc < 32; cc++) {
            const float2 zv = *(const float2*)&zr[(size_t)cc * BN];
            const ull u0 = pk2(zv.x, zv.x);
            const ull u1 = pk2(zv.y, zv.y);
#pragma unroll
            for (int jj = 0; jj < 4; jj++) {
                const ulonglong2 w2 = *(const ulonglong2*)&wp[cc][opb + 2 * jj];
                acc0[2 * jj]     = ff2(u0, w2.x, acc0[2 * jj]);
                acc1[2 * jj]     = ff2(u1, w2.x, acc1[2 * jj]);
                acc0[2 * jj + 1] = ff2(u0, w2.y, acc0[2 * jj + 1]);
                acc1[2 * jj + 1] = ff2(u1, w2.y, acc1[2 * jj + 1]);
            }
        }
        // transpose into smem: sT[row][m][o]
#pragma unroll
        for (int j = 0; j < 8; j++) {
            const int op = opb + j;
            float l0, h0, l1, h1;
            up2(acc0[j], l0, h0);
            up2(acc1[j], l1, h1);
            sT[row][m0 * ST_LD + 2 * op]           = l0;
            sT[row][m0 * ST_LD + 2 * op + 1]       = h0;
            sT[row][(m0 + 1) * ST_LD + 2 * op]     = l1;
            sT[row][(m0 + 1) * ST_LD + 2 * op + 1] = h1;
        }
    }
    __syncthreads();
#pragma unroll
    for (int k = 0; k < 8; k++) {
        const int j = (k * 128 + tid) * 4;
        const int mr = j >> 5, o = j & 31;
        *(float4*)&out[bA * 4096 + j]       = *(const float4*)&sT[0][mr * ST_LD + o];
        *(float4*)&out[(bA + 1) * 4096 + j] = *(const float4*)&sT[1][mr * ST_LD + o];
    }
}

// ---------------- launch ----------------
extern "C" void kernel_launch(void* const* d_in, const int* in_sizes, int n_in,
                              void* d_out, int out_size) {
    (void)in_sizes; (void)n_in; (void)out_size;
    const float* x      = (const float*)d_in[0];
    const float* W_in   = (const float*)d_in[1];
    const float* b_in   = (const float*)d_in[2];
    const float* W_mods = (const float*)d_in[3];
    const float* b_mods = (const float*)d_in[4];
    const float* W_out  = (const float*)d_in[5];
    const float* b_out  = (const float*)d_in[6];
    float* out = (float*)d_out;

    const int smem2 = SMEM2_FLOATS * (int)sizeof(float);  // 86528 bytes
    cudaFuncSetAttribute(k_stage2, cudaFuncAttributeMaxDynamicSharedMemorySize, smem2);

    k_stage1<<<BATCH / 2, 128>>>(x, W_in, b_in);
    k_stage2<<<dim3(BATCH / 128, NBLK), 256, smem2>>>(W_mods, b_mods);
    k_stage3<<<BATCH / 2, 128>>>(W_out, b_out, out);
}

// round 14
// speedup vs baseline: 1.4677x; 1.2845x over previous
#include <cuda_runtime.h>
#include <cstdint>

// Problem constants
#define BATCH   8192
#define MSIZE   128
#define NBLK    32                 // ICOUNT = MCOUNT = OCOUNT
#define BN      (BATCH * MSIZE)    // 1048576 elems per c-slab

// Scratch: Y[c][b][n] (tf32), Z[b][c][m] (tf32-ready fp32)  (128 MB each)
__device__ float g_Y[(size_t)NBLK * BN];
__device__ float g_Z[(size_t)NBLK * BN];

// ---------------- helpers ----------------
__device__ __forceinline__ float tf32r(float v) {
    unsigned u;
    asm("cvt.rna.tf32.f32 %0, %1;" : "=r"(u) : "f"(v));
    return __uint_as_float(u);
}
__device__ __forceinline__ void mma_tf32(float& d0, float& d1, float& d2, float& d3,
                                         unsigned a0, unsigned a1, unsigned a2, unsigned a3,
                                         unsigned b0, unsigned b1) {
    asm volatile(
        "mma.sync.aligned.m16n8k8.row.col.f32.tf32.tf32.f32 "
        "{%0,%1,%2,%3}, {%4,%5,%6,%7}, {%8,%9}, {%0,%1,%2,%3};"
        : "+f"(d0), "+f"(d1), "+f"(d2), "+f"(d3)
        : "r"(a0), "r"(a1), "r"(a2), "r"(a3), "r"(b0), "r"(b1));
}

// ---------------- Stage 1 (tf32 MMA) ----------------
// D[bn, c] = sum_i x[b, i*128+n] * W_in[c,i] + b_in[c];  Y[c][b][n] = tf32(D)
// CTA: 256 threads, M-tile = 256 bn-rows (2 batch rows), N=32, K=32.
#define A1_LD 260   // As[i][bl*128+n], k-major rows
#define B1_LD 36
__global__ void __launch_bounds__(256) k1_mma(const float* __restrict__ x,
                                              const float* __restrict__ Win,
                                              const float* __restrict__ bin) {
    __shared__ float As[32 * A1_LD];
    __shared__ float Bs[32 * B1_LD];
    __shared__ float bb[32];
    const int tid = threadIdx.x;
    const size_t b0 = (size_t)blockIdx.x * 2;

    // stage x (2 contiguous rows = 32KB), tf32-rounded, into As[i][bl*128+n]
    const float4* x4 = (const float4*)(x + b0 * 4096);
#pragma unroll
    for (int j = 0; j < 8; j++) {
        const int idx = tid + j * 256;         // 0..2047
        const int bl = idx >> 10, q = idx & 1023;
        const int i = q >> 5, n4 = (q & 31) << 2;
        float4 v = x4[idx];
        v.x = tf32r(v.x); v.y = tf32r(v.y); v.z = tf32r(v.z); v.w = tf32r(v.w);
        *(float4*)&As[i * A1_LD + bl * 128 + n4] = v;
    }
    // stage W_in [c][i] (already B-fragment layout), tf32-rounded
    {
        const int c = tid >> 3, i4 = (tid & 7) << 2;
        float4 w = *(const float4*)&Win[c * 32 + i4];
        w.x = tf32r(w.x); w.y = tf32r(w.y); w.z = tf32r(w.z); w.w = tf32r(w.w);
        *(float4*)&Bs[c * B1_LD + i4] = w;
    }
    if (tid < 32) bb[tid] = bin[tid];
    __syncthreads();

    const int lane = tid & 31, warp = tid >> 5;
    const int g = lane >> 2, tg = lane & 3;
    const int wr = warp * 32;

    float acc[2][4][4];
#pragma unroll
    for (int rt = 0; rt < 2; rt++)
#pragma unroll
        for (int ct = 0; ct < 4; ct++)
#pragma unroll
            for (int j = 0; j < 4; j++) acc[rt][ct][j] = 0.0f;

#pragma unroll
    for (int ks = 0; ks < 4; ks++) {
        const int kk = ks * 8 + tg;
        unsigned a0[2], a1[2], a2[2], a3[2], bf0[4], bf1[4];
#pragma unroll
        for (int rt = 0; rt < 2; rt++) {
            const int r0 = wr + rt * 16 + g;
            a0[rt] = __float_as_uint(As[kk * A1_LD + r0]);
            a1[rt] = __float_as_uint(As[kk * A1_LD + r0 + 8]);
            a2[rt] = __float_as_uint(As[(kk + 4) * A1_LD + r0]);
            a3[rt] = __float_as_uint(As[(kk + 4) * A1_LD + r0 + 8]);
        }
#pragma unroll
        for (int ct = 0; ct < 4; ct++) {
            const int col = ct * 8 + g;
            bf0[ct] = __float_as_uint(Bs[col * B1_LD + ks * 8 + tg]);
            bf1[ct] = __float_as_uint(Bs[col * B1_LD + ks * 8 + tg + 4]);
        }
#pragma unroll
        for (int rt = 0; rt < 2; rt++)
#pragma unroll
            for (int ct = 0; ct < 4; ct++)
                mma_tf32(acc[rt][ct][0], acc[rt][ct][1], acc[rt][ct][2], acc[rt][ct][3],
                         a0[rt], a1[rt], a2[rt], a3[rt], bf0[ct], bf1[ct]);
    }

    // epilogue: Y[c][b][n] = tf32(acc + b_in[c])
#pragma unroll
    for (int rt = 0; rt < 2; rt++) {
        const int rA = wr + rt * 16 + g;        // and rA+8, same bl
        const int bl = rA >> 7, nA = rA & 127, nB = (rA + 8) & 127;
        const size_t bo = (b0 + bl) * 128;
#pragma unroll
        for (int ct = 0; ct < 4; ct++) {
            const int c0 = ct * 8 + tg * 2;
            g_Y[(size_t)c0 * BN + bo + nA]       = tf32r(acc[rt][ct][0] + bb[c0]);
            g_Y[(size_t)(c0 + 1) * BN + bo + nA] = tf32r(acc[rt][ct][1] + bb[c0 + 1]);
            g_Y[(size_t)c0 * BN + bo + nB]       = tf32r(acc[rt][ct][2] + bb[c0]);
            g_Y[(size_t)(c0 + 1) * BN + bo + nB] = tf32r(acc[rt][ct][3] + bb[c0 + 1]);
        }
    }
}

// ---------------- Stage 2 (R7 config; epilogue -> Z[b][c][m]) ----------------
// per c: Z[b][c][m] = sum_n Y[c][b][n] * W_mods[c][m][n] + b_mods[c][m]
#define AS_LD 132
#define BS_LD 36
#define SMEM2_FLOATS (128 * AS_LD + 128 * BS_LD + 128)

__global__ void __launch_bounds__(256, 2) k_stage2(const float* __restrict__ Wm,
                                                   const float* __restrict__ bmods) {
    extern __shared__ float sm[];
    float* As  = sm;                             // [128][AS_LD]
    float* Bs  = sm + 128 * AS_LD;               // [128][BS_LD]
    float* bmS = sm + 128 * AS_LD + 128 * BS_LD; // [128]

    const int tid = threadIdx.x;
    const int c   = blockIdx.y;
    const int bt  = blockIdx.x;

    const float* Wc = Wm + (size_t)c * 16384;

    float4 pre[4];
#pragma unroll
    for (int j = 0; j < 4; j++) {
        const int i = tid + j * 256;
        const int mm = i >> 3, cc = (i & 7) << 2;
        pre[j] = *(const float4*)(Wc + mm * 128 + cc);
    }

    const float4* As4 = (const float4*)(g_Y + (size_t)c * BN + (size_t)bt * 16384);
#pragma unroll
    for (int i = tid; i < 4096; i += 256) {
        const int r = i >> 5, cc = (i & 31) << 2;
        *(float4*)&As[r * AS_LD + cc] = As4[i];
    }
    if (tid < 128) bmS[tid] = bmods[c * 128 + tid];

    const int lane = tid & 31, warp = tid >> 5;
    const int g = lane >> 2, tg = lane & 3;
    const int wr = (warp & 1) * 64;
    const int wc = (warp >> 1) * 32;

    float acc[4][4][4];
#pragma unroll
    for (int rt = 0; rt < 4; rt++)
#pragma unroll
        for (int ct = 0; ct < 4; ct++)
#pragma unroll
            for (int j = 0; j < 4; j++) acc[rt][ct][j] = 0.0f;

#pragma unroll 1
    for (int kc = 0; kc < 4; kc++) {
        __syncthreads();
#pragma unroll
        for (int j = 0; j < 4; j++) {
            const int i = tid + j * 256;
            const int mm = i >> 3, cc = (i & 7) << 2;
            float4 v = pre[j];
            v.x = tf32r(v.x); v.y = tf32r(v.y); v.z = tf32r(v.z); v.w = tf32r(v.w);
            *(float4*)&Bs[mm * BS_LD + cc] = v;
        }
        __syncthreads();
        if (kc < 3) {
#pragma unroll
            for (int j = 0; j < 4; j++) {
                const int i = tid + j * 256;
                const int mm = i >> 3, cc = (i & 7) << 2;
                pre[j] = *(const float4*)(Wc + mm * 128 + (kc + 1) * 32 + cc);
            }
        }

#pragma unroll
        for (int ks = 0; ks < 4; ks++) {
            const int kA = kc * 32 + ks * 8;
            const int kB = ks * 8;
            unsigned a0[4], a1[4], a2[4], a3[4], b0[4], b1[4];
#pragma unroll
            for (int rt = 0; rt < 4; rt++) {
                const int r0 = wr + rt * 16 + g;
                a0[rt] = __float_as_uint(As[r0 * AS_LD + kA + tg]);
                a1[rt] = __float_as_uint(As[(r0 + 8) * AS_LD + kA + tg]);
                a2[rt] = __float_as_uint(As[r0 * AS_LD + kA + tg + 4]);
                a3[rt] = __float_as_uint(As[(r0 + 8) * AS_LD + kA + tg + 4]);
            }
#pragma unroll
            for (int ct = 0; ct < 4; ct++) {
                const int mcol = wc + ct * 8 + g;
                b0[ct] = __float_as_uint(Bs[mcol * BS_LD + kB + tg]);
                b1[ct] = __float_as_uint(Bs[mcol * BS_LD + kB + tg + 4]);
            }
#pragma unroll
            for (int rt = 0; rt < 4; rt++)
#pragma unroll
                for (int ct = 0; ct < 4; ct++)
                    mma_tf32(acc[rt][ct][0], acc[rt][ct][1], acc[rt][ct][2], acc[rt][ct][3],
                             a0[rt], a1[rt], a2[rt], a3[rt], b0[ct], b1[ct]);
        }
    }

    // epilogue: add bias, write Z[b][c][m]  (b-major layout for stage 3)
#pragma unroll
    for (int rt = 0; rt < 4; rt++) {
        const int r0 = wr + rt * 16 + g;
        const size_t base = ((size_t)bt * 128 + r0) * 4096 + (size_t)c * 128;
#pragma unroll
        for (int ct = 0; ct < 4; ct++) {
            const int m0 = wc + ct * 8 + tg * 2;
            const float bv0 = bmS[m0], bv1 = bmS[m0 + 1];
            float2 v0 = make_float2(acc[rt][ct][0] + bv0, acc[rt][ct][1] + bv1);
            float2 v1 = make_float2(acc[rt][ct][2] + bv0, acc[rt][ct][3] + bv1);
            *(float2*)&g_Z[base + m0]            = v0;   // row b = bt*128+r0
            *(float2*)&g_Z[base + 8 * 4096 + m0] = v1;   // row +8
        }
    }
}

// ---------------- Stage 3 (tf32 MMA) ----------------
// D[bm, o] = sum_c Z[b][c][m] * W_out[o,c] + b_out[o];  out[b][m*32+o] = D (contiguous!)
#define A3_LD 260
#define B3_LD 36
__global__ void __launch_bounds__(256) k3_mma(const float* __restrict__ Wout,
                                              const float* __restrict__ bout,
                                              float* __restrict__ out) {
    __shared__ float As[32 * A3_LD];   // [c][bl*128+m]
    __shared__ float Bs[32 * B3_LD];   // [o][c]
    __shared__ float bb[32];
    const int tid = threadIdx.x;
    const size_t b0 = (size_t)blockIdx.x * 2;

    // stage Z (2 contiguous rows of [c][m] = 32KB), tf32-rounded
    const float4* z4 = (const float4*)(g_Z + b0 * 4096);
#pragma unroll
    for (int j = 0; j < 8; j++) {
        const int idx = tid + j * 256;         // 0..2047
        const int bl = idx >> 10, q = idx & 1023;
        const int c = q >> 5, m4 = (q & 31) << 2;
        float4 v = z4[idx];
        v.x = tf32r(v.x); v.y = tf32r(v.y); v.z = tf32r(v.z); v.w = tf32r(v.w);
        *(float4*)&As[c * A3_LD + bl * 128 + m4] = v;
    }
    {
        const int o = tid >> 3, c4 = (tid & 7) << 2;
        float4 w = *(const float4*)&Wout[o * 32 + c4];
        w.x = tf32r(w.x); w.y = tf32r(w.y); w.z = tf32r(w.z); w.w = tf32r(w.w);
        *(float4*)&Bs[o * B3_LD + c4] = w;
    }
    if (tid < 32) bb[tid] = bout[tid];
    __syncthreads();

    const int lane = tid & 31, warp = tid >> 5;
    const int g = lane >> 2, tg = lane & 3;
    const int wr = warp * 32;

    float acc[2][4][4];
#pragma unroll
    for (int rt = 0; rt < 2; rt++)
#pragma unroll
        for (int ct = 0; ct < 4; ct++)
#pragma unroll
            for (int j = 0; j < 4; j++) acc[rt][ct][j] = 0.0f;

#pragma unroll
    for (int ks = 0; ks < 4; ks++) {
        const int kk = ks * 8 + tg;
        unsigned a0[2], a1[2], a2[2], a3[2], bf0[4], bf1[4];
#pragma unroll
        for (int rt = 0; rt < 2; rt++) {
            const int r0 = wr + rt * 16 + g;
            a0[rt] = __float_as_uint(As[kk * A3_LD + r0]);
            a1[rt] = __float_as_uint(As[kk * A3_LD + r0 + 8]);
            a2[rt] = __float_as_uint(As[(kk + 4) * A3_LD + r0]);
            a3[rt] = __float_as_uint(As[(kk + 4) * A3_LD + r0 + 8]);
        }
#pragma unroll
        for (int ct = 0; ct < 4; ct++) {
            const int col = ct * 8 + g;
            bf0[ct] = __float_as_uint(Bs[col * B3_LD + ks * 8 + tg]);
            bf1[ct] = __float_as_uint(Bs[col * B3_LD + ks * 8 + tg + 4]);
        }
#pragma unroll
        for (int rt = 0; rt < 2; rt++)
#pragma unroll
            for (int ct = 0; ct < 4; ct++)
                mma_tf32(acc[rt][ct][0], acc[rt][ct][1], acc[rt][ct][2], acc[rt][ct][3],
                         a0[rt], a1[rt], a2[rt], a3[rt], bf0[ct], bf1[ct]);
    }

    // epilogue: out[b][m*32+o] (contiguous float2 stores)
#pragma unroll
    for (int rt = 0; rt < 2; rt++) {
        const int rA = wr + rt * 16 + g;        // and rA+8, same bl
        const int bl = rA >> 7, mA = rA & 127, mB = (rA + 8) & 127;
        float* orow = out + (b0 + bl) * 4096;
#pragma unroll
        for (int ct = 0; ct < 4; ct++) {
            const int o0 = ct * 8 + tg * 2;
            const float bv0 = bb[o0], bv1 = bb[o0 + 1];
            *(float2*)&orow[mA * 32 + o0] = make_float2(acc[rt][ct][0] + bv0, acc[rt][ct][1] + bv1);
            *(float2*)&orow[mB * 32 + o0] = make_float2(acc[rt][ct][2] + bv0, acc[rt][ct][3] + bv1);
        }
    }
}

// ---------------- launch ----------------
extern "C" void kernel_launch(void* const* d_in, const int* in_sizes, int n_in,
                              void* d_out, int out_size) {
    (void)in_sizes; (void)n_in; (void)out_size;
    const float* x      = (const float*)d_in[0];
    const float* W_in   = (const float*)d_in[1];
    const float* b_in   = (const float*)d_in[2];
    const float* W_mods = (const float*)d_in[3];
    const float* b_mods = (const float*)d_in[4];
    const float* W_out  = (const float*)d_in[5];
    const float* b_out  = (const float*)d_in[6];
    float* out = (float*)d_out;

    const int smem2 = SMEM2_FLOATS * (int)sizeof(float);  // 86528 bytes
    cudaFuncSetAttribute(k_stage2, cudaFuncAttributeMaxDynamicSharedMemorySize, smem2);

    k1_mma  <<<BATCH / 2, 256>>>(x, W_in, b_in);
    k_stage2<<<dim3(BATCH / 128, NBLK), 256, smem2>>>(W_mods, b_mods);
    k3_mma  <<<BATCH / 2, 256>>>(W_out, b_out, out);
}